// round 7
// baseline (speedup 1.0000x reference)
#include <cuda_runtime.h>
#include <cuda_bf16.h>

#define N_NODES 100000
#define N_EDGES 1600000

// ---------------- scratch: __device__ globals, referenced directly -----------
__device__ __align__(16) float g_h[N_NODES * 64];     // GEMM output / gather src
__device__ __align__(16) float g_agg[N_NODES * 64];   // aggregation output
__device__ float g_dinv[N_NODES];
__device__ int   g_deg[N_NODES];
__device__ int   g_cur[N_NODES];
__device__ int   g_off[N_NODES + 1];
__device__ int   g_src[N_EDGES];
__device__ int   g_dst[N_EDGES];
__device__ float g_norm[N_EDGES];
__device__ int   g_csrc[N_EDGES];
__device__ __align__(16) float g_cnorm[N_EDGES];
__device__ int   g_is64;                              // edge_index dtype flag

// ---------------- dtype detection --------------------------------------------
// int64 edge values < 2^31: every odd 32-bit word (high half) is 0.
// int32 values uniform in [0,100000): odd words are ~never all zero.
__global__ void k_detect(const int* __restrict__ ei) {
    __shared__ int nonzero;
    if (threadIdx.x == 0) nonzero = 0;
    __syncthreads();
    if (ei[2 * threadIdx.x + 1] != 0) atomicAdd(&nonzero, 1);
    __syncthreads();
    if (threadIdx.x == 0) g_is64 = (nonzero == 0) ? 1 : 0;
}

__device__ __forceinline__ int edge_src(const int* ei, int e) {
    return g_is64 ? ei[2 * e] : ei[e];
}
__device__ __forceinline__ int edge_dst(const int* ei, int e) {
    return g_is64 ? ei[2 * (N_EDGES + e)] : ei[N_EDGES + e];
}

// ---------------- degree / norm precompute ----------------------------------
__global__ void k_deg_zero() {
    int i = blockIdx.x * blockDim.x + threadIdx.x;
    if (i < N_NODES) { g_deg[i] = 0; g_cur[i] = 0; }
}

__global__ void k_count(const int* __restrict__ ei) {
    int e = blockIdx.x * blockDim.x + threadIdx.x;
    if (e < N_EDGES) {
        int d = edge_dst(ei, e);
        if ((unsigned)d < N_NODES) atomicAdd(&g_deg[d], 1);
    }
}

__global__ void k_dinv() {
    int i = blockIdx.x * blockDim.x + threadIdx.x;
    if (i < N_NODES) g_dinv[i] = rsqrtf((float)(g_deg[i] + 1));  // +1: self-loop
}

__global__ void k_prep(const int* __restrict__ ei) {
    int e = blockIdx.x * blockDim.x + threadIdx.x;
    if (e < N_EDGES) {
        int s = edge_src(ei, e);
        int d = edge_dst(ei, e);
        if ((unsigned)s >= N_NODES) s = 0;
        if ((unsigned)d >= N_NODES) d = 0;
        g_src[e] = s;
        g_dst[e] = d;
        g_norm[e] = g_dinv[s] * g_dinv[d];
    }
}

// ---------------- single-block prefix scan of degrees -> row offsets ---------
__global__ void k_scan() {
    __shared__ int partial[1024];
    const int tid = threadIdx.x;
    const int chunk = (N_NODES + 1023) / 1024;  // 98
    const int start = tid * chunk;
    const int end = min(start + chunk, N_NODES);

    int s = 0;
    for (int i = start; i < end; i++) s += g_deg[i];
    partial[tid] = s;
    __syncthreads();

    for (int off = 1; off < 1024; off <<= 1) {
        int v = 0;
        if (tid >= off) v = partial[tid - off];
        __syncthreads();
        partial[tid] += v;
        __syncthreads();
    }

    int run = (tid > 0) ? partial[tid - 1] : 0;  // exclusive base
    for (int i = start; i < end; i++) {
        g_off[i] = run;
        run += g_deg[i];
    }
    if (start < N_NODES && end == N_NODES) g_off[N_NODES] = run;
}

// ---------------- edge placement into CSR ------------------------------------
__global__ void k_place() {
    int e = blockIdx.x * blockDim.x + threadIdx.x;
    if (e < N_EDGES) {
        int d = g_dst[e];
        int pos = g_off[d] + atomicAdd(&g_cur[d], 1);
        g_csrc[pos] = g_src[e];
        g_cnorm[pos] = g_norm[e];
    }
}

// ---------------- GEMM: [32 rows] x [64 -> OUT] ------------------------------
// FROM_X: read input from param x; else read from g_agg (with ReLU applied).
template <int OUT, bool FROM_X>
__global__ void k_gemm(const float* __restrict__ x, const float* __restrict__ W) {
    constexpr int QUADS = OUT / 4;
    constexpr int RPT = (32 * QUADS) / 256;  // 2 for OUT=64, 1 for OUT=32
    __shared__ float Ws[64 * OUT];
    __shared__ float xs[32][65];  // pad to kill stride-64 bank conflicts

    const int tid = threadIdx.x;
    const int row0 = blockIdx.x * 32;  // N_NODES % 32 == 0

    for (int i = tid; i < 64 * OUT; i += 256) Ws[i] = W[i];

    for (int i = tid; i < 32 * 16; i += 256) {
        int r = i >> 4, c4 = i & 15;
        float4 v;
        if (FROM_X) {
            v = *(const float4*)&x[(size_t)(row0 + r) * 64 + c4 * 4];
        } else {
            v = *(const float4*)&g_agg[(size_t)(row0 + r) * 64 + c4 * 4];
            v.x = fmaxf(v.x, 0.f); v.y = fmaxf(v.y, 0.f);
            v.z = fmaxf(v.z, 0.f); v.w = fmaxf(v.w, 0.f);
        }
        xs[r][c4 * 4 + 0] = v.x; xs[r][c4 * 4 + 1] = v.y;
        xs[r][c4 * 4 + 2] = v.z; xs[r][c4 * 4 + 3] = v.w;
    }
    __syncthreads();

    const int colq = tid % QUADS;
    const int rg = tid / QUADS;

    float acc[RPT][4];
#pragma unroll
    for (int r = 0; r < RPT; r++) { acc[r][0] = acc[r][1] = acc[r][2] = acc[r][3] = 0.f; }

#pragma unroll
    for (int k = 0; k < 64; k++) {
        float4 w = *(const float4*)&Ws[k * OUT + colq * 4];
#pragma unroll
        for (int r = 0; r < RPT; r++) {
            float xv = xs[rg * RPT + r][k];
            acc[r][0] = fmaf(xv, w.x, acc[r][0]);
            acc[r][1] = fmaf(xv, w.y, acc[r][1]);
            acc[r][2] = fmaf(xv, w.z, acc[r][2]);
            acc[r][3] = fmaf(xv, w.w, acc[r][3]);
        }
    }

#pragma unroll
    for (int r = 0; r < RPT; r++) {
        int row = row0 + rg * RPT + r;
        *(float4*)&g_h[(size_t)row * OUT + colq * 4] =
            make_float4(acc[r][0], acc[r][1], acc[r][2], acc[r][3]);
    }
}

// ---------------- CSR aggregation: one warp per node -------------------------
// dst[node] = dinv^2 * h[node] + b + sum_{edges into node} norm * h[src]
template <int OUT, bool TO_OUT>
__global__ void k_agg(const float* __restrict__ b, float* __restrict__ out) {
    constexpr int C = OUT / 32;  // 2 for 64, 1 for 32
    const int warp = (blockIdx.x * blockDim.x + threadIdx.x) >> 5;
    const int lane = threadIdx.x & 31;
    if (warp >= N_NODES) return;
    const int node = warp;

    float acc[C];
    {
        float di = g_dinv[node];
        float sc = di * di;
#pragma unroll
        for (int c = 0; c < C; c++)
            acc[c] = sc * g_h[(size_t)node * OUT + lane + 32 * c] + b[lane + 32 * c];
    }

    const int beg = g_off[node];
    const int end = g_off[node + 1];
    for (int p = beg; p < end; p++) {
        int s = g_csrc[p];          // warp-uniform
        float nz = g_cnorm[p];
#pragma unroll
        for (int c = 0; c < C; c++)
            acc[c] = fmaf(nz, g_h[(size_t)s * OUT + lane + 32 * c], acc[c]);
    }

    if (TO_OUT) {
#pragma unroll
        for (int c = 0; c < C; c++)
            out[(size_t)node * OUT + lane + 32 * c] = acc[c];
    } else {
#pragma unroll
        for (int c = 0; c < C; c++)
            g_agg[(size_t)node * OUT + lane + 32 * c] = acc[c];
    }
}

// ---------------- launch: kernel launches ONLY --------------------------------
extern "C" void kernel_launch(void* const* d_in, const int* in_sizes, int n_in,
                              void* d_out, int out_size) {
    const float* x  = (const float*)d_in[0];
    const int* ei   = (const int*)d_in[1];   // int32 (JAX x64 off) or int64 (auto-detected)
    const float* W1 = (const float*)d_in[2];
    const float* b1 = (const float*)d_in[3];
    const float* W2 = (const float*)d_in[4];
    const float* b2 = (const float*)d_in[5];
    const float* W3 = (const float*)d_in[6];
    const float* b3 = (const float*)d_in[7];
    float* out      = (float*)d_out;

    const int T = 256;
    const int gN = (N_NODES + T - 1) / T;
    const int gE = (N_EDGES + T - 1) / T;
    const int gW = (N_NODES * 32 + T - 1) / T;  // one warp per node

    // dtype detect + CSR build
    k_detect<<<1, 256>>>(ei);
    k_deg_zero<<<gN, T>>>();
    k_count<<<gE, T>>>(ei);
    k_dinv<<<gN, T>>>();
    k_prep<<<gE, T>>>(ei);
    k_scan<<<1, 1024>>>();
    k_place<<<gE, T>>>();

    // Layer 1: h = x @ W1 ; agg
    k_gemm<64, true><<<N_NODES / 32, T>>>(x, W1);
    k_agg<64, false><<<gW, T>>>(b1, nullptr);

    // Layer 2: h = relu(agg) @ W2 ; agg
    k_gemm<64, false><<<N_NODES / 32, T>>>(nullptr, W2);
    k_agg<64, false><<<gW, T>>>(b2, nullptr);

    // Layer 3: h = relu(agg) @ W3 (OUT=32) ; agg -> d_out
    k_gemm<32, false><<<N_NODES / 32, T>>>(nullptr, W3);
    k_agg<32, true><<<gW, T>>>(b3, out);
}